// round 14
// baseline (speedup 1.0000x reference)
#include <cuda_runtime.h>
#include <cuda_bf16.h>
#include <math.h>
#include <stdint.h>

#define N_NODES 20000
#define MPAD    20096     // 157*128
#define HDIM    512
#define FEAT    1029
#define NUM_GAT 5
#define E_CAP   360000

#define K2_FEAT 528    // 33 chunks of 16 k2-rows (K=1056)
#define K2_H    256    // 16 chunks
#define OFF_W1   0
#define OFF_V1   (K2_FEAT)
#define OFF_W2   (2*K2_FEAT)
#define OFF_W3   (OFF_W2 + K2_H)
#define OFF_V2   (OFF_W3 + K2_H)
#define OFF_GAT0 (OFF_V2 + K2_H)
#define K2_TOTAL (OFF_GAT0 + 5*K2_H)

#define NBLK_PERSIST 296   // 2 CTAs/SM x 148 SMs
#define NTILES 628         // 4 col-blocks x 157 row-blocks

// ---------------- scratch (device globals; no allocation) ----------------
__device__ float    g_h   [(size_t)N_NODES * HDIM];
__device__ float    g_hw  [(size_t)N_NODES * HDIM];
__device__ float    g_acc [(size_t)N_NODES * HDIM];
__device__ float    g_s   [N_NODES];
__device__ float    g_t   [N_NODES];
__device__ int      g_cnt [N_NODES];
__device__ int      g_off [N_NODES + 1];
__device__ int      g_cur [N_NODES];
__device__ int      g_dsts[E_CAP];
__device__ int      g_srcs[E_CAP];
__device__ uint32_t g_Bh  [(size_t)K2_TOTAL * HDIM];   // permuted: [q8][n][j]
__device__ uint32_t g_Bl  [(size_t)K2_TOTAL * HDIM];
__device__ uint32_t g_A1h [(size_t)K2_FEAT * MPAD];    // permuted m within 16-groups
__device__ uint32_t g_A1l [(size_t)K2_FEAT * MPAD];
__device__ uint32_t g_A2h [(size_t)K2_H * MPAD];
__device__ uint32_t g_A2l [(size_t)K2_H * MPAD];

// ---------------- split ALL weights (B-permuted layout) ----------------
__global__ void split_all(const float* __restrict__ W1, const float* __restrict__ V1,
                          const float* __restrict__ W2, const float* __restrict__ W3,
                          const float* __restrict__ V2, const float* __restrict__ gatW,
                          uint32_t* __restrict__ Bh, uint32_t* __restrict__ Bl) {
    int idx = blockIdx.x * blockDim.x + threadIdx.x;
    if (idx >= K2_TOTAL * HDIM) return;
    int k2g = idx >> 9, n = idx & 511;
    const float* src; int KB, k2l;
    if (k2g < K2_FEAT)            { src = W1; k2l = k2g;            KB = FEAT; }
    else if (k2g < 2 * K2_FEAT)   { src = V1; k2l = k2g - K2_FEAT;  KB = FEAT; }
    else {
        int r = k2g - 2 * K2_FEAT;
        int w = r >> 8; k2l = r & 255; KB = HDIM;
        src = (w == 0) ? W2 : (w == 1) ? W3 : (w == 2) ? V2
                                            : gatW + (size_t)(w - 3) * HDIM * HDIM;
    }
    int k = 2 * k2l;
    float x0 = (k     < KB) ? src[(size_t)k * HDIM + n]       : 0.f;
    float x1 = (k + 1 < KB) ? src[(size_t)(k + 1) * HDIM + n] : 0.f;
    float h0 = __bfloat162float(__float2bfloat16(x0));
    float h1 = __bfloat162float(__float2bfloat16(x1));
    __nv_bfloat162 hp = __floats2bfloat162_rn(x0, x1);
    __nv_bfloat162 lp = __floats2bfloat162_rn(x0 - h0, x1 - h1);
    int wbase = (k2g - k2l) << 9;
    int q8 = k2l >> 3, r = k2l & 7;
    int j = ((r & 3) << 1) | (r >> 2);
    size_t o = (size_t)wbase + (size_t)q8 * 4096 + n * 8 + j;
    Bh[o] = *reinterpret_cast<uint32_t*>(&hp);
    Bl[o] = *reinterpret_cast<uint32_t*>(&lp);
}

// ---------------- activation convert fp32 -> split bf16x2 [k2][pm(MPAD)] ----------
template <int CAT>
__global__ __launch_bounds__(256)
void conv_a(const float* __restrict__ A, const float* __restrict__ goal,
            const float* __restrict__ info, uint32_t* __restrict__ Ah,
            uint32_t* __restrict__ Al, int M, int Kdim) {
    __shared__ float tile[128][33];
    const int tid = threadIdx.x;
    const int m0 = blockIdx.x * 128;
    const int k0 = blockIdx.y * 32;
    const int ml = tid & 127, half = tid >> 7;
    const int gm = m0 + ml;
    #pragma unroll
    for (int i = 0; i < 4; i++) {
        int kk = k0 + half * 16 + i * 4;
        float4 v = make_float4(0.f, 0.f, 0.f, 0.f);
        if (gm < M) {
            if (CAT == 0) {
                if (kk + 3 < Kdim)
                    v = *reinterpret_cast<const float4*>(A + (size_t)gm * Kdim + kk);
            } else {
                if (kk < 512)
                    v = *reinterpret_cast<const float4*>(A + (size_t)gm * 512 + kk);
                else if (kk < 1024)
                    v = *reinterpret_cast<const float4*>(goal + (size_t)gm * 512 + kk - 512);
                else if (kk == 1024) {
                    const float* ir = info + (size_t)gm * 5;
                    v = make_float4(ir[0], ir[1], ir[2], ir[3]);
                } else if (kk == 1028) {
                    v.x = info[(size_t)gm * 5 + 4];
                }
            }
        }
        int cb = half * 16 + i * 4;
        tile[ml][cb + 0] = v.x; tile[ml][cb + 1] = v.y;
        tile[ml][cb + 2] = v.z; tile[ml][cb + 3] = v.w;
    }
    __syncthreads();
    const int k2l = tid >> 4, mq = tid & 15;
    const size_t k2g = blockIdx.y * 16 + k2l;
    #pragma unroll
    for (int j = 0; j < 8; j++) {
        int m = mq + j * 16;
        float x0 = tile[m][2 * k2l], x1 = tile[m][2 * k2l + 1];
        float h0 = __bfloat162float(__float2bfloat16(x0));
        float h1 = __bfloat162float(__float2bfloat16(x1));
        __nv_bfloat162 hp = __floats2bfloat162_rn(x0, x1);
        __nv_bfloat162 lp = __floats2bfloat162_rn(x0 - h0, x1 - h1);
        int pm = j * 16 + ((mq & 7) << 1) + (mq >> 3);
        size_t o = k2g * MPAD + m0 + pm;
        Ah[o] = *reinterpret_cast<uint32_t*>(&hp);
        Al[o] = *reinterpret_cast<uint32_t*>(&lp);
    }
}

// ================= persistent pipelined split-bf16 GEMM =================
#define TBM 128
#define TBN 128
#define ASTR 136
#define SM_AH(s) ((s) * 8704)
#define SM_AL(s) (17408 + (s) * 8704)
#define SM_BH(s) (34816 + (s) * 8192)
#define SM_BL(s) (51200 + (s) * 8192)
#define SM_BYTES 67584

__device__ __forceinline__ uint32_t smem_u32(const void* p) {
    uint32_t a;
    asm("{ .reg .u64 t; cvta.to.shared.u64 t, %1; cvt.u32.u64 %0, t; }" : "=r"(a) : "l"(p));
    return a;
}
__device__ __forceinline__ void mma_bf16(float* c, const uint32_t* a, const uint32_t* b) {
    asm("mma.sync.aligned.m16n8k16.row.col.f32.bf16.bf16.f32 "
        "{%0,%1,%2,%3}, {%4,%5,%6,%7}, {%8,%9}, {%0,%1,%2,%3};"
        : "+f"(c[0]), "+f"(c[1]), "+f"(c[2]), "+f"(c[3])
        : "r"(a[0]), "r"(a[1]), "r"(a[2]), "r"(a[3]), "r"(b[0]), "r"(b[1]));
}
__device__ __forceinline__ void cp16(uint32_t dst, const void* src) {
    asm volatile("cp.async.cg.shared.global [%0], [%1], 16;" :: "r"(dst), "l"(src));
}

// OUT: 0 = fp32 C ; 1 = split bf16x2 (permuted).  DOTS: s/t partials.
template <int ACT, int OUT, int DOTS>
__global__ __launch_bounds__(256, 2)
void gemm_pp(const uint32_t* __restrict__ Ah, const uint32_t* __restrict__ Al,
             const uint32_t* __restrict__ Bh, const uint32_t* __restrict__ Bl,
             const float* __restrict__ bias, float* __restrict__ C,
             uint32_t* __restrict__ Aoh, uint32_t* __restrict__ Aol,
             const float* __restrict__ av, float* __restrict__ sv,
             float* __restrict__ tv, int M, int nch) {
    extern __shared__ char smem[];
    const uint32_t sb = smem_u32(smem);
    const int tid  = threadIdx.x;
    const int lane = tid & 31;
    const int wid  = tid >> 5;
    const int lq   = lane >> 2, lr = lane & 3;
    const int wm   = (wid & 3) * 32;
    const int wn   = (wid >> 2) * 64;

    auto loadStage = [&](int row0, int col0, int ch, int s) {
        #pragma unroll
        for (int it = 0; it < 2; it++) {
            int f = tid + it * 256;
            {
                int r2 = f >> 5, q = f & 31;
                size_t gA = (size_t)(ch * 16 + r2) * MPAD + row0 + q * 4;
                uint32_t dA = (uint32_t)((r2 * ASTR + q * 4) * 4);
                cp16(sb + SM_AH(s) + dA, Ah + gA);
                cp16(sb + SM_AL(s) + dA, Al + gA);
            }
            {
                int q8l = f >> 8, rest = f & 255;
                int nl = rest >> 1, j4 = rest & 1;
                size_t gB = (size_t)(ch * 2 + q8l) * 4096 + (size_t)(col0 + nl) * 8 + j4 * 4;
                uint32_t dB = (uint32_t)((q8l * 1024 + nl * 8 + j4 * 4) * 4);
                cp16(sb + SM_BH(s) + dB, Bh + gB);
                cp16(sb + SM_BL(s) + dB, Bl + gB);
            }
        }
        asm volatile("cp.async.commit_group;");
    };

    // persistent loop over output tiles; column-major order (B reuse in L2)
    for (int tile = blockIdx.x; tile < NTILES; tile += NBLK_PERSIST) {
        const int bx = tile / 157, by = tile - bx * 157;
        const int row0 = by * TBM, col0 = bx * TBN;

        float c[2][8][4] = {};

        loadStage(row0, col0, 0, 0);

        for (int ch = 0; ch < nch; ch++) {
            int cur = ch & 1, nxt = cur ^ 1;
            bool more = (ch + 1 < nch);
            if (more) {
                loadStage(row0, col0, ch + 1, nxt);
                asm volatile("cp.async.wait_group 1;");
            } else {
                asm volatile("cp.async.wait_group 0;");
            }
            __syncthreads();

            const uint32_t* AHp = reinterpret_cast<uint32_t*>(smem + SM_AH(cur));
            const uint32_t* ALp = reinterpret_cast<uint32_t*>(smem + SM_AL(cur));
            const uint32_t* BHp = reinterpret_cast<uint32_t*>(smem + SM_BH(cur));
            const uint32_t* BLp = reinterpret_cast<uint32_t*>(smem + SM_BL(cur));

            #pragma unroll
            for (int ks2 = 0; ks2 < 16; ks2 += 8) {
                const int q8l = ks2 >> 3;
                uint32_t ah[2][4], al[2][4];
                #pragma unroll
                for (int ma = 0; ma < 2; ma++) {
                    int base = wm + ma * 16 + lq * 2;
                    int kA0 = (ks2 + lr) * ASTR, kA1 = (ks2 + lr + 4) * ASTR;
                    uint2 h0 = *reinterpret_cast<const uint2*>(&AHp[kA0 + base]);
                    uint2 h1 = *reinterpret_cast<const uint2*>(&AHp[kA1 + base]);
                    uint2 l0 = *reinterpret_cast<const uint2*>(&ALp[kA0 + base]);
                    uint2 l1 = *reinterpret_cast<const uint2*>(&ALp[kA1 + base]);
                    ah[ma][0] = h0.x; ah[ma][1] = h0.y; ah[ma][2] = h1.x; ah[ma][3] = h1.y;
                    al[ma][0] = l0.x; al[ma][1] = l0.y; al[ma][2] = l1.x; al[ma][3] = l1.y;
                }
                #pragma unroll
                for (int ng = 0; ng < 2; ng++) {
                    uint32_t bh[4][2], bl[4][2];
                    #pragma unroll
                    for (int nb = 0; nb < 4; nb++) {
                        int ncol = wn + (ng * 4 + nb) * 8 + lq;
                        int boff = q8l * 1024 + ncol * 8 + lr * 2;
                        uint2 bhv = *reinterpret_cast<const uint2*>(&BHp[boff]);
                        uint2 blv = *reinterpret_cast<const uint2*>(&BLp[boff]);
                        bh[nb][0] = bhv.x; bh[nb][1] = bhv.y;
                        bl[nb][0] = blv.x; bl[nb][1] = blv.y;
                    }
                    #pragma unroll
                    for (int ma = 0; ma < 2; ma++) {
                        #pragma unroll
                        for (int nb = 0; nb < 4; nb++) {
                            float* cc = c[ma][ng * 4 + nb];
                            mma_bf16(cc, ah[ma], bh[nb]);
                            mma_bf16(cc, ah[ma], bl[nb]);
                            mma_bf16(cc, al[ma], bh[nb]);
                        }
                    }
                }
            }
            __syncthreads();
        }

        // ---- per-tile epilogue ----
        float sp[2][2] = {}, tp[2][2] = {};
        #pragma unroll
        for (int na = 0; na < 8; na++) {
            int gn = col0 + wn + na * 8 + 2 * lr;
            float b0 = bias ? bias[gn]     : 0.f;
            float b1 = bias ? bias[gn + 1] : 0.f;
            float a10 = 0.f, a11 = 0.f, a20 = 0.f, a21 = 0.f;
            if (DOTS) {
                a10 = av[gn]; a11 = av[gn + 1];
                a20 = av[HDIM + gn]; a21 = av[HDIM + gn + 1];
            }
            #pragma unroll
            for (int ma = 0; ma < 2; ma++) {
                int gm = row0 + wm + ma * 16 + lq;
                float v0 = c[ma][na][0] + b0;
                float v1 = c[ma][na][1] + b1;
                float v2 = c[ma][na][2] + b0;
                float v3 = c[ma][na][3] + b1;
                if (ACT == 1) {
                    v0 = fmaxf(v0, 0.f); v1 = fmaxf(v1, 0.f);
                    v2 = fmaxf(v2, 0.f); v3 = fmaxf(v3, 0.f);
                }
                if (DOTS) {
                    sp[ma][0] += v0 * a10 + v1 * a11;
                    sp[ma][1] += v2 * a10 + v3 * a11;
                    tp[ma][0] += v0 * a20 + v1 * a21;
                    tp[ma][1] += v2 * a20 + v3 * a21;
                }
                if (OUT == 0) {
                    if (gm < M)
                        *reinterpret_cast<float2*>(C + (size_t)gm * HDIM + gn) = make_float2(v0, v1);
                    if (gm + 8 < M)
                        *reinterpret_cast<float2*>(C + (size_t)(gm + 8) * HDIM + gn) = make_float2(v2, v3);
                } else {
                    size_t o = (size_t)(gn >> 1) * MPAD + (row0 + wm + ma * 16) + 2 * lq;
                    float h0 = __bfloat162float(__float2bfloat16(v0));
                    float h1 = __bfloat162float(__float2bfloat16(v1));
                    __nv_bfloat162 hpA = __floats2bfloat162_rn(v0, v1);
                    __nv_bfloat162 lpA = __floats2bfloat162_rn(v0 - h0, v1 - h1);
                    float h2 = __bfloat162float(__float2bfloat16(v2));
                    float h3 = __bfloat162float(__float2bfloat16(v3));
                    __nv_bfloat162 hpB = __floats2bfloat162_rn(v2, v3);
                    __nv_bfloat162 lpB = __floats2bfloat162_rn(v2 - h2, v3 - h3);
                    uint2 uh, ul;
                    uh.x = *reinterpret_cast<uint32_t*>(&hpA);
                    uh.y = *reinterpret_cast<uint32_t*>(&hpB);
                    ul.x = *reinterpret_cast<uint32_t*>(&lpA);
                    ul.y = *reinterpret_cast<uint32_t*>(&lpB);
                    *reinterpret_cast<uint2*>(Aoh + o) = uh;
                    *reinterpret_cast<uint2*>(Aol + o) = ul;
                }
            }
        }
        if (DOTS) {
            #pragma unroll
            for (int ma = 0; ma < 2; ma++) {
                #pragma unroll
                for (int r = 0; r < 2; r++) {
                    sp[ma][r] += __shfl_down_sync(0xffffffffu, sp[ma][r], 1);
                    sp[ma][r] += __shfl_down_sync(0xffffffffu, sp[ma][r], 2);
                    tp[ma][r] += __shfl_down_sync(0xffffffffu, tp[ma][r], 1);
                    tp[ma][r] += __shfl_down_sync(0xffffffffu, tp[ma][r], 2);
                }
            }
            if (lr == 0) {
                #pragma unroll
                for (int ma = 0; ma < 2; ma++) {
                    int gm = row0 + wm + ma * 16 + lq;
                    if (gm < M)     { atomicAdd(&sv[gm], sp[ma][0]);     atomicAdd(&tv[gm], tp[ma][0]); }
                    if (gm + 8 < M) { atomicAdd(&sv[gm + 8], sp[ma][1]); atomicAdd(&tv[gm + 8], tp[ma][1]); }
                }
            }
        }
        __syncthreads();   // all reads of smem done before next tile's prologue
    }
}

// ================= CSR build =================
__global__ void zero2(int* __restrict__ a, int* __restrict__ b, int n) {
    int i = blockIdx.x * blockDim.x + threadIdx.x;
    if (i < n) { a[i] = 0; b[i] = 0; }
}
__global__ void zero_st(float* __restrict__ s, float* __restrict__ t, int n) {
    int i = blockIdx.x * blockDim.x + threadIdx.x;
    if (i < n) { s[i] = 0.f; t[i] = 0.f; }
}
__global__ void csr_count(const int* __restrict__ src, int* __restrict__ cnt, int E) {
    int i = blockIdx.x * blockDim.x + threadIdx.x;
    if (i < E) atomicAdd(&cnt[src[i]], 1);
}
__global__ void csr_scan(const int* __restrict__ cnt, int* __restrict__ off, int n) {
    __shared__ int sh[1024];
    const int tid = threadIdx.x;
    const int seg = (n + 1023) / 1024;
    const int beg = tid * seg;
    int local[20];
    int sum = 0;
    #pragma unroll
    for (int j = 0; j < 20; j++) {
        int i = beg + j;
        int v = (j < seg && i < n) ? cnt[i] : 0;
        local[j] = sum;
        sum += v;
    }
    sh[tid] = sum;
    __syncthreads();
    #pragma unroll
    for (int o = 1; o < 1024; o <<= 1) {
        int x = (tid >= o) ? sh[tid - o] : 0;
        __syncthreads();
        sh[tid] += x;
        __syncthreads();
    }
    int base = (tid > 0) ? sh[tid - 1] : 0;
    #pragma unroll
    for (int j = 0; j < 20; j++) {
        int i = beg + j;
        if (j < seg && i < n) off[i] = base + local[j];
    }
    if (tid == 1023) off[n] = sh[1023];
}
__global__ void csr_place(const int* __restrict__ src, const int* __restrict__ dst,
                          const int* __restrict__ off, int* __restrict__ cur,
                          int* __restrict__ dsts, int* __restrict__ srcs, int E) {
    int i = blockIdx.x * blockDim.x + threadIdx.x;
    if (i >= E) return;
    int u = src[i];
    int p = off[u] + atomicAdd(&cur[u], 1);
    dsts[p] = dst[i];
    srcs[p] = u;
}

// ---------------- GAT aggregation (fused edge scores, windowed smem) ----------------
__global__ void gat_aggregate(const int* __restrict__ off, const int* __restrict__ dsts,
                              const float* __restrict__ s, const float* __restrict__ t,
                              const float* __restrict__ hw, float* __restrict__ hout) {
    __shared__ float sh_e[512];
    int u = blockIdx.x;
    int c = threadIdx.x;
    int beg = off[u], end = off[u + 1];
    float su = s[u];
    float4 acc = make_float4(0.f, 0.f, 0.f, 0.f);
    float dsum = 0.f;
    for (int w = beg; w < end; w += 512) {
        int we = w + 512 < end ? w + 512 : end;
        for (int j = w + c; j < we; j += 128) {
            float sc = su + t[dsts[j]];
            float lr = sc > 0.f ? sc : 0.2f * sc;
            sh_e[j - w] = expf(-lr);
        }
        __syncthreads();
        int p = w;
        for (; p + 1 < we; p += 2) {
            int d0 = dsts[p], d1 = dsts[p + 1];
            float e0 = sh_e[p - w], e1 = sh_e[p + 1 - w];
            float4 v0 = *(reinterpret_cast<const float4*>(hw + (size_t)d0 * HDIM) + c);
            float4 v1 = *(reinterpret_cast<const float4*>(hw + (size_t)d1 * HDIM) + c);
            dsum += e0 + e1;
            acc.x += e0 * v0.x + e1 * v1.x;
            acc.y += e0 * v0.y + e1 * v1.y;
            acc.z += e0 * v0.z + e1 * v1.z;
            acc.w += e0 * v0.w + e1 * v1.w;
        }
        if (p < we) {
            int d = dsts[p];
            float ev = sh_e[p - w];
            float4 v = *(reinterpret_cast<const float4*>(hw + (size_t)d * HDIM) + c);
            dsum += ev;
            acc.x += ev * v.x; acc.y += ev * v.y;
            acc.z += ev * v.z; acc.w += ev * v.w;
        }
        __syncthreads();
    }
    float inv = 1.f / (dsum + 1e-10f);
    float4 o;
    o.x = fmaxf(acc.x * inv, 0.f);
    o.y = fmaxf(acc.y * inv, 0.f);
    o.z = fmaxf(acc.z * inv, 0.f);
    o.w = fmaxf(acc.w * inv, 0.f);
    *(reinterpret_cast<float4*>(hout + (size_t)u * HDIM) + c) = o;
}

// ---------------- final GEMV + sigmoid ----------------
__global__ void gemv_sigmoid(const float* __restrict__ h2, const float* __restrict__ v3,
                             const float* __restrict__ vb3, float* __restrict__ out, int n) {
    int warp = (blockIdx.x * blockDim.x + threadIdx.x) >> 5;
    int lane = threadIdx.x & 31;
    if (warp >= n) return;
    const float* row = h2 + (size_t)warp * HDIM;
    float acc = 0.f;
    #pragma unroll 4
    for (int c = lane; c < HDIM; c += 32) acc += row[c] * v3[c];
    #pragma unroll
    for (int o = 16; o; o >>= 1) acc += __shfl_down_sync(0xffffffffu, acc, o);
    if (lane == 0) {
        float x = acc + vb3[0];
        out[warp] = 1.f / (1.f + expf(-x));
    }
}

// ---------------- host launcher ----------------
extern "C" void kernel_launch(void* const* d_in, const int* in_sizes, int n_in,
                              void* d_out, int out_size) {
    const float* feat = (const float*)d_in[0];
    const float* goal = (const float*)d_in[1];
    const float* info = (const float*)d_in[2];
    const int*   esrc = (const int*)d_in[3];
    const int*   edst = (const int*)d_in[4];
    const float* W1   = (const float*)d_in[5];
    const float* b1   = (const float*)d_in[6];
    const float* W2   = (const float*)d_in[7];
    const float* b2   = (const float*)d_in[8];
    const float* W3   = (const float*)d_in[9];
    const float* b3   = (const float*)d_in[10];
    const float* V1   = (const float*)d_in[11];
    const float* vb1  = (const float*)d_in[12];
    const float* V2   = (const float*)d_in[13];
    const float* vb2  = (const float*)d_in[14];
    const float* V3   = (const float*)d_in[15];
    const float* vb3  = (const float*)d_in[16];
    const float* gatW = (const float*)d_in[17];
    const float* gatA = (const float*)d_in[18];
    float* out = (float*)d_out;

    int E = in_sizes[3];
    if (E > E_CAP) E = E_CAP;
    const int n = N_NODES;

    float *h, *hw, *acc, *s, *t;
    int *cnt, *off, *cur, *dsts, *srcs;
    uint32_t *Bh, *Bl, *A1h, *A1l, *A2h, *A2l;
    cudaGetSymbolAddress((void**)&h,   g_h);
    cudaGetSymbolAddress((void**)&hw,  g_hw);
    cudaGetSymbolAddress((void**)&acc, g_acc);
    cudaGetSymbolAddress((void**)&s,   g_s);
    cudaGetSymbolAddress((void**)&t,   g_t);
    cudaGetSymbolAddress((void**)&cnt, g_cnt);
    cudaGetSymbolAddress((void**)&off, g_off);
    cudaGetSymbolAddress((void**)&cur, g_cur);
    cudaGetSymbolAddress((void**)&dsts,g_dsts);
    cudaGetSymbolAddress((void**)&srcs,g_srcs);
    cudaGetSymbolAddress((void**)&Bh,  g_Bh);
    cudaGetSymbolAddress((void**)&Bl,  g_Bl);
    cudaGetSymbolAddress((void**)&A1h, g_A1h);
    cudaGetSymbolAddress((void**)&A1l, g_A1l);
    cudaGetSymbolAddress((void**)&A2h, g_A2h);
    cudaGetSymbolAddress((void**)&A2l, g_A2l);

    static bool attr_done = false;
    if (!attr_done) {
        cudaFuncSetAttribute(gemm_pp<1,1,0>, cudaFuncAttributeMaxDynamicSharedMemorySize, SM_BYTES);
        cudaFuncSetAttribute(gemm_pp<0,1,0>, cudaFuncAttributeMaxDynamicSharedMemorySize, SM_BYTES);
        cudaFuncSetAttribute(gemm_pp<0,0,1>, cudaFuncAttributeMaxDynamicSharedMemorySize, SM_BYTES);
        cudaFuncSetAttribute(gemm_pp<1,0,0>, cudaFuncAttributeMaxDynamicSharedMemorySize, SM_BYTES);
        attr_done = true;
    }

    const dim3 gg(NBLK_PERSIST);
    const dim3 cg_f(157, K2_FEAT / 16);
    const dim3 cg_h(157, K2_H / 16);
    const int node_warp_blocks = (n * 32 + 255) / 256;
    const int edge_blocks = (E + 255) / 256;

    #define BW(o) (Bh + (size_t)(o) * HDIM), (Bl + (size_t)(o) * HDIM)

    // ---- input chain ----
    split_all<<<(K2_TOTAL * HDIM + 255) / 256, 256>>>(W1, V1, W2, W3, V2, gatW, Bh, Bl);
    conv_a<1><<<cg_f, 256>>>(feat, goal, info, A1h, A1l, n, FEAT);
    gemm_pp<1,1,0><<<gg, 256, SM_BYTES>>>(A1h, A1l, BW(OFF_W1), b1, nullptr, A2h, A2l,
                                          nullptr, nullptr, nullptr, n, K2_FEAT / 16);
    gemm_pp<1,1,0><<<gg, 256, SM_BYTES>>>(A2h, A2l, BW(OFF_W2), b2, nullptr, A1h, A1l,
                                          nullptr, nullptr, nullptr, n, K2_H / 16);
    gemm_pp<0,1,0><<<gg, 256, SM_BYTES>>>(A1h, A1l, BW(OFF_W3), b3, nullptr, A2h, A2l,
                                          nullptr, nullptr, nullptr, n, K2_H / 16);

    // ---- CSR build ----
    zero2<<<(n + 255) / 256, 256>>>(cnt, cur, n);
    csr_count<<<edge_blocks, 256>>>(esrc, cnt, E);
    csr_scan<<<1, 1024>>>(cnt, off, n);
    csr_place<<<edge_blocks, 256>>>(esrc, edst, off, cur, dsts, srcs, E);

    // ---- GAT layers ----
    for (int l = 0; l < NUM_GAT; l++) {
        const float* al = gatA + (size_t)l * 2 * HDIM;
        zero_st<<<(n + 255) / 256, 256>>>(s, t, n);
        gemm_pp<0,0,1><<<gg, 256, SM_BYTES>>>(A2h, A2l, BW(OFF_GAT0 + l * K2_H),
                                              nullptr, hw, nullptr, nullptr,
                                              al, s, t, n, K2_H / 16);
        gat_aggregate<<<n, 128>>>(off, dsts, s, t, hw, h);
        if (l < NUM_GAT - 1)
            conv_a<0><<<cg_h, 256>>>(h, nullptr, nullptr, A2h, A2l, n, HDIM);
    }

    // ---- output MLP ----
    conv_a<1><<<cg_f, 256>>>(h, goal, info, A1h, A1l, n, FEAT);
    gemm_pp<1,1,0><<<gg, 256, SM_BYTES>>>(A1h, A1l, BW(OFF_V1), vb1, nullptr, A2h, A2l,
                                          nullptr, nullptr, nullptr, n, K2_FEAT / 16);
    gemm_pp<1,0,0><<<gg, 256, SM_BYTES>>>(A2h, A2l, BW(OFF_V2), vb2, acc, nullptr, nullptr,
                                          nullptr, nullptr, nullptr, n, K2_H / 16);
    gemv_sigmoid<<<node_warp_blocks, 256>>>(acc, V3, vb3, out, n);
}

// round 17
// speedup vs baseline: 1.0040x; 1.0040x over previous
#include <cuda_runtime.h>
#include <cuda_bf16.h>
#include <math.h>
#include <stdint.h>

#define N_NODES 20000
#define MPAD    20096     // 157*128
#define HDIM    512
#define FEAT    1029
#define NUM_GAT 5
#define E_CAP   360000

#define K2_FEAT 528    // 33 chunks of 16 k2-rows (K=1056)
#define K2_H    256    // 16 chunks
#define OFF_W1   0
#define OFF_V1   (K2_FEAT)
#define OFF_W2   (2*K2_FEAT)
#define OFF_W3   (OFF_W2 + K2_H)
#define OFF_V2   (OFF_W3 + K2_H)
#define OFF_GAT0 (OFF_V2 + K2_H)
#define K2_TOTAL (OFF_GAT0 + 5*K2_H)

#define NBLK_PERSIST 296   // 2 CTAs/SM x 148 SMs
#define NTILES 628         // 4 col-blocks x 157 row-blocks

// ---------------- scratch (device globals; no allocation) ----------------
__device__ float    g_h   [(size_t)N_NODES * HDIM];
__device__ float    g_hw  [(size_t)N_NODES * HDIM];
__device__ float    g_acc [(size_t)N_NODES * HDIM];
__device__ float    g_sp  [4 * MPAD];   // per-column-block dot partials (s)
__device__ float    g_tp  [4 * MPAD];   // per-column-block dot partials (t)
__device__ int      g_cnt [N_NODES];
__device__ int      g_off [N_NODES + 1];
__device__ int      g_cur [N_NODES];
__device__ int      g_dsts[E_CAP];
__device__ int      g_srcs[E_CAP];
__device__ uint32_t g_Bh  [(size_t)K2_TOTAL * HDIM];   // permuted: [q8][n][j]
__device__ uint32_t g_Bl  [(size_t)K2_TOTAL * HDIM];
__device__ uint32_t g_A1h [(size_t)K2_FEAT * MPAD];    // permuted m within 16-groups
__device__ uint32_t g_A1l [(size_t)K2_FEAT * MPAD];
__device__ uint32_t g_A2h [(size_t)K2_H * MPAD];
__device__ uint32_t g_A2l [(size_t)K2_H * MPAD];

// ---------------- split ALL weights (B-permuted layout) ----------------
__global__ void split_all(const float* __restrict__ W1, const float* __restrict__ V1,
                          const float* __restrict__ W2, const float* __restrict__ W3,
                          const float* __restrict__ V2, const float* __restrict__ gatW,
                          uint32_t* __restrict__ Bh, uint32_t* __restrict__ Bl) {
    int idx = blockIdx.x * blockDim.x + threadIdx.x;
    if (idx >= K2_TOTAL * HDIM) return;
    int k2g = idx >> 9, n = idx & 511;
    const float* src; int KB, k2l;
    if (k2g < K2_FEAT)            { src = W1; k2l = k2g;            KB = FEAT; }
    else if (k2g < 2 * K2_FEAT)   { src = V1; k2l = k2g - K2_FEAT;  KB = FEAT; }
    else {
        int r = k2g - 2 * K2_FEAT;
        int w = r >> 8; k2l = r & 255; KB = HDIM;
        src = (w == 0) ? W2 : (w == 1) ? W3 : (w == 2) ? V2
                                            : gatW + (size_t)(w - 3) * HDIM * HDIM;
    }
    int k = 2 * k2l;
    float x0 = (k     < KB) ? src[(size_t)k * HDIM + n]       : 0.f;
    float x1 = (k + 1 < KB) ? src[(size_t)(k + 1) * HDIM + n] : 0.f;
    float h0 = __bfloat162float(__float2bfloat16(x0));
    float h1 = __bfloat162float(__float2bfloat16(x1));
    __nv_bfloat162 hp = __floats2bfloat162_rn(x0, x1);
    __nv_bfloat162 lp = __floats2bfloat162_rn(x0 - h0, x1 - h1);
    int wbase = (k2g - k2l) << 9;
    int q8 = k2l >> 3, r = k2l & 7;
    int j = ((r & 3) << 1) | (r >> 2);
    size_t o = (size_t)wbase + (size_t)q8 * 4096 + n * 8 + j;
    Bh[o] = *reinterpret_cast<uint32_t*>(&hp);
    Bl[o] = *reinterpret_cast<uint32_t*>(&lp);
}

// ---------------- activation convert fp32 -> split bf16x2 [k2][pm(MPAD)] ----------
template <int CAT>
__global__ __launch_bounds__(256)
void conv_a(const float* __restrict__ A, const float* __restrict__ goal,
            const float* __restrict__ info, uint32_t* __restrict__ Ah,
            uint32_t* __restrict__ Al, int M, int Kdim) {
    __shared__ float tile[128][33];
    const int tid = threadIdx.x;
    const int m0 = blockIdx.x * 128;
    const int k0 = blockIdx.y * 32;
    const int ml = tid & 127, half = tid >> 7;
    const int gm = m0 + ml;
    #pragma unroll
    for (int i = 0; i < 4; i++) {
        int kk = k0 + half * 16 + i * 4;
        float4 v = make_float4(0.f, 0.f, 0.f, 0.f);
        if (gm < M) {
            if (CAT == 0) {
                if (kk + 3 < Kdim)
                    v = *reinterpret_cast<const float4*>(A + (size_t)gm * Kdim + kk);
            } else {
                if (kk < 512)
                    v = *reinterpret_cast<const float4*>(A + (size_t)gm * 512 + kk);
                else if (kk < 1024)
                    v = *reinterpret_cast<const float4*>(goal + (size_t)gm * 512 + kk - 512);
                else if (kk == 1024) {
                    const float* ir = info + (size_t)gm * 5;
                    v = make_float4(ir[0], ir[1], ir[2], ir[3]);
                } else if (kk == 1028) {
                    v.x = info[(size_t)gm * 5 + 4];
                }
            }
        }
        int cb = half * 16 + i * 4;
        tile[ml][cb + 0] = v.x; tile[ml][cb + 1] = v.y;
        tile[ml][cb + 2] = v.z; tile[ml][cb + 3] = v.w;
    }
    __syncthreads();
    const int k2l = tid >> 4, mq = tid & 15;
    const size_t k2g = blockIdx.y * 16 + k2l;
    #pragma unroll
    for (int j = 0; j < 8; j++) {
        int m = mq + j * 16;
        float x0 = tile[m][2 * k2l], x1 = tile[m][2 * k2l + 1];
        float h0 = __bfloat162float(__float2bfloat16(x0));
        float h1 = __bfloat162float(__float2bfloat16(x1));
        __nv_bfloat162 hp = __floats2bfloat162_rn(x0, x1);
        __nv_bfloat162 lp = __floats2bfloat162_rn(x0 - h0, x1 - h1);
        int pm = j * 16 + ((mq & 7) << 1) + (mq >> 3);
        size_t o = k2g * MPAD + m0 + pm;
        Ah[o] = *reinterpret_cast<uint32_t*>(&hp);
        Al[o] = *reinterpret_cast<uint32_t*>(&lp);
    }
}

// ================= persistent pipelined split-bf16 GEMM =================
#define TBM 128
#define TBN 128
#define ASTR 136
#define SM_AH(s) ((s) * 8704)
#define SM_AL(s) (17408 + (s) * 8704)
#define SM_BH(s) (34816 + (s) * 8192)
#define SM_BL(s) (51200 + (s) * 8192)
#define SM_BYTES 67584

__device__ __forceinline__ uint32_t smem_u32(const void* p) {
    uint32_t a;
    asm("{ .reg .u64 t; cvta.to.shared.u64 t, %1; cvt.u32.u64 %0, t; }" : "=r"(a) : "l"(p));
    return a;
}
__device__ __forceinline__ void mma_bf16(float* c, const uint32_t* a, const uint32_t* b) {
    asm("mma.sync.aligned.m16n8k16.row.col.f32.bf16.bf16.f32 "
        "{%0,%1,%2,%3}, {%4,%5,%6,%7}, {%8,%9}, {%0,%1,%2,%3};"
        : "+f"(c[0]), "+f"(c[1]), "+f"(c[2]), "+f"(c[3])
        : "r"(a[0]), "r"(a[1]), "r"(a[2]), "r"(a[3]), "r"(b[0]), "r"(b[1]));
}
__device__ __forceinline__ void cp16(uint32_t dst, const void* src) {
    asm volatile("cp.async.cg.shared.global [%0], [%1], 16;" :: "r"(dst), "l"(src));
}

// OUT: 0 = fp32 C ; 1 = split bf16x2 (permuted).  DOTS: per-block dot partials.
template <int ACT, int OUT, int DOTS>
__global__ __launch_bounds__(256, 2)
void gemm_pp(const uint32_t* __restrict__ Ah, const uint32_t* __restrict__ Al,
             const uint32_t* __restrict__ Bh, const uint32_t* __restrict__ Bl,
             const float* __restrict__ bias, float* __restrict__ C,
             uint32_t* __restrict__ Aoh, uint32_t* __restrict__ Aol,
             const float* __restrict__ av, float* __restrict__ sv,
             float* __restrict__ tv, int M, int nch) {
    extern __shared__ char smem[];
    const uint32_t sb = smem_u32(smem);
    const int tid  = threadIdx.x;
    const int lane = tid & 31;
    const int wid  = tid >> 5;
    const int lq   = lane >> 2, lr = lane & 3;
    const int wm   = (wid & 3) * 32;
    const int wn   = (wid >> 2) * 64;

    auto loadStage = [&](int row0, int col0, int ch, int s) {
        #pragma unroll
        for (int it = 0; it < 2; it++) {
            int f = tid + it * 256;
            {
                int r2 = f >> 5, q = f & 31;
                size_t gA = (size_t)(ch * 16 + r2) * MPAD + row0 + q * 4;
                uint32_t dA = (uint32_t)((r2 * ASTR + q * 4) * 4);
                cp16(sb + SM_AH(s) + dA, Ah + gA);
                cp16(sb + SM_AL(s) + dA, Al + gA);
            }
            {
                int q8l = f >> 8, rest = f & 255;
                int nl = rest >> 1, j4 = rest & 1;
                size_t gB = (size_t)(ch * 2 + q8l) * 4096 + (size_t)(col0 + nl) * 8 + j4 * 4;
                uint32_t dB = (uint32_t)((q8l * 1024 + nl * 8 + j4 * 4) * 4);
                cp16(sb + SM_BH(s) + dB, Bh + gB);
                cp16(sb + SM_BL(s) + dB, Bl + gB);
            }
        }
        asm volatile("cp.async.commit_group;");
    };

    // persistent loop over output tiles; column-major order (B reuse in L2)
    for (int tile = blockIdx.x; tile < NTILES; tile += NBLK_PERSIST) {
        const int bx = tile / 157, by = tile - bx * 157;
        const int row0 = by * TBM, col0 = bx * TBN;

        float c[2][8][4] = {};

        loadStage(row0, col0, 0, 0);

        for (int ch = 0; ch < nch; ch++) {
            int cur = ch & 1;
            asm volatile("cp.async.wait_group 0;");
            __syncthreads();               // all warps done reading buffer cur^1
            if (ch + 1 < nch)
                loadStage(row0, col0, ch + 1, cur ^ 1);   // in flight during compute

            const uint32_t* AHp = reinterpret_cast<uint32_t*>(smem + SM_AH(cur));
            const uint32_t* ALp = reinterpret_cast<uint32_t*>(smem + SM_AL(cur));
            const uint32_t* BHp = reinterpret_cast<uint32_t*>(smem + SM_BH(cur));
            const uint32_t* BLp = reinterpret_cast<uint32_t*>(smem + SM_BL(cur));

            #pragma unroll
            for (int ks2 = 0; ks2 < 16; ks2 += 8) {
                const int q8l = ks2 >> 3;
                uint32_t ah[2][4], al[2][4];
                #pragma unroll
                for (int ma = 0; ma < 2; ma++) {
                    int base = wm + ma * 16 + lq * 2;
                    int kA0 = (ks2 + lr) * ASTR, kA1 = (ks2 + lr + 4) * ASTR;
                    uint2 h0 = *reinterpret_cast<const uint2*>(&AHp[kA0 + base]);
                    uint2 h1 = *reinterpret_cast<const uint2*>(&AHp[kA1 + base]);
                    uint2 l0 = *reinterpret_cast<const uint2*>(&ALp[kA0 + base]);
                    uint2 l1 = *reinterpret_cast<const uint2*>(&ALp[kA1 + base]);
                    ah[ma][0] = h0.x; ah[ma][1] = h0.y; ah[ma][2] = h1.x; ah[ma][3] = h1.y;
                    al[ma][0] = l0.x; al[ma][1] = l0.y; al[ma][2] = l1.x; al[ma][3] = l1.y;
                }
                #pragma unroll
                for (int ng = 0; ng < 2; ng++) {
                    uint32_t bh[4][2], bl[4][2];
                    #pragma unroll
                    for (int nb = 0; nb < 4; nb++) {
                        int ncol = wn + (ng * 4 + nb) * 8 + lq;
                        int boff = q8l * 1024 + ncol * 8 + lr * 2;
                        uint2 bhv = *reinterpret_cast<const uint2*>(&BHp[boff]);
                        uint2 blv = *reinterpret_cast<const uint2*>(&BLp[boff]);
                        bh[nb][0] = bhv.x; bh[nb][1] = bhv.y;
                        bl[nb][0] = blv.x; bl[nb][1] = blv.y;
                    }
                    #pragma unroll
                    for (int ma = 0; ma < 2; ma++) {
                        #pragma unroll
                        for (int nb = 0; nb < 4; nb++) {
                            float* cc = c[ma][ng * 4 + nb];
                            mma_bf16(cc, ah[ma], bh[nb]);
                            mma_bf16(cc, ah[ma], bl[nb]);
                            mma_bf16(cc, al[ma], bh[nb]);
                        }
                    }
                }
            }
        }

        // ---- per-tile epilogue (registers + global only; no smem) ----
        float sp[2][2] = {}, tp[2][2] = {};
        #pragma unroll
        for (int na = 0; na < 8; na++) {
            int gn = col0 + wn + na * 8 + 2 * lr;
            float b0 = bias ? bias[gn]     : 0.f;
            float b1 = bias ? bias[gn + 1] : 0.f;
            float a10 = 0.f, a11 = 0.f, a20 = 0.f, a21 = 0.f;
            if (DOTS) {
                a10 = av[gn]; a11 = av[gn + 1];
                a20 = av[HDIM + gn]; a21 = av[HDIM + gn + 1];
            }
            #pragma unroll
            for (int ma = 0; ma < 2; ma++) {
                int gm = row0 + wm + ma * 16 + lq;
                float v0 = c[ma][na][0] + b0;
                float v1 = c[ma][na][1] + b1;
                float v2 = c[ma][na][2] + b0;
                float v3 = c[ma][na][3] + b1;
                if (ACT == 1) {
                    v0 = fmaxf(v0, 0.f); v1 = fmaxf(v1, 0.f);
                    v2 = fmaxf(v2, 0.f); v3 = fmaxf(v3, 0.f);
                }
                if (DOTS) {
                    sp[ma][0] += v0 * a10 + v1 * a11;
                    sp[ma][1] += v2 * a10 + v3 * a11;
                    tp[ma][0] += v0 * a20 + v1 * a21;
                    tp[ma][1] += v2 * a20 + v3 * a21;
                }
                if (OUT == 0) {
                    if (gm < M)
                        *reinterpret_cast<float2*>(C + (size_t)gm * HDIM + gn) = make_float2(v0, v1);
                    if (gm + 8 < M)
                        *reinterpret_cast<float2*>(C + (size_t)(gm + 8) * HDIM + gn) = make_float2(v2, v3);
                } else {
                    size_t o = (size_t)(gn >> 1) * MPAD + (row0 + wm + ma * 16) + 2 * lq;
                    float h0 = __bfloat162float(__float2bfloat16(v0));
                    float h1 = __bfloat162float(__float2bfloat16(v1));
                    __nv_bfloat162 hpA = __floats2bfloat162_rn(v0, v1);
                    __nv_bfloat162 lpA = __floats2bfloat162_rn(v0 - h0, v1 - h1);
                    float h2 = __bfloat162float(__float2bfloat16(v2));
                    float h3 = __bfloat162float(__float2bfloat16(v3));
                    __nv_bfloat162 hpB = __floats2bfloat162_rn(v2, v3);
                    __nv_bfloat162 lpB = __floats2bfloat162_rn(v2 - h2, v3 - h3);
                    uint2 uh, ul;
                    uh.x = *reinterpret_cast<uint32_t*>(&hpA);
                    uh.y = *reinterpret_cast<uint32_t*>(&hpB);
                    ul.x = *reinterpret_cast<uint32_t*>(&lpA);
                    ul.y = *reinterpret_cast<uint32_t*>(&lpB);
                    *reinterpret_cast<uint2*>(Aoh + o) = uh;
                    *reinterpret_cast<uint2*>(Aol + o) = ul;
                }
            }
        }
        if (DOTS) {
            #pragma unroll
            for (int ma = 0; ma < 2; ma++) {
                #pragma unroll
                for (int r = 0; r < 2; r++) {
                    sp[ma][r] += __shfl_down_sync(0xffffffffu, sp[ma][r], 1);
                    sp[ma][r] += __shfl_down_sync(0xffffffffu, sp[ma][r], 2);
                    tp[ma][r] += __shfl_down_sync(0xffffffffu, tp[ma][r], 1);
                    tp[ma][r] += __shfl_down_sync(0xffffffffu, tp[ma][r], 2);
                }
            }
            if (lr == 0) {
                #pragma unroll
                for (int ma = 0; ma < 2; ma++) {
                    int gm = row0 + wm + ma * 16 + lq;
                    atomicAdd(&sv[(size_t)bx * MPAD + gm], sp[ma][0]);
                    atomicAdd(&tv[(size_t)bx * MPAD + gm], tp[ma][0]);
                    atomicAdd(&sv[(size_t)bx * MPAD + gm + 8], sp[ma][1]);
                    atomicAdd(&tv[(size_t)bx * MPAD + gm + 8], tp[ma][1]);
                }
            }
        }
        __syncthreads();   // smem reads of last chunk done before next tile's prologue
    }
}

// ---------------- zero the dot-partial buffers (1 launch per GAT layer) --------
__global__ void zero_sp(float* __restrict__ sv, float* __restrict__ tv) {
    int i = blockIdx.x * blockDim.x + threadIdx.x;
    if (i < 4 * MPAD) { sv[i] = 0.f; tv[i] = 0.f; }
}

// ================= CSR build =================
__global__ void zero2(int* __restrict__ a, int* __restrict__ b, int n) {
    int i = blockIdx.x * blockDim.x + threadIdx.x;
    if (i < n) { a[i] = 0; b[i] = 0; }
}
__global__ void csr_count(const int* __restrict__ src, int* __restrict__ cnt, int E) {
    int i = blockIdx.x * blockDim.x + threadIdx.x;
    if (i < E) atomicAdd(&cnt[src[i]], 1);
}
__global__ void csr_scan(const int* __restrict__ cnt, int* __restrict__ off, int n) {
    __shared__ int sh[1024];
    const int tid = threadIdx.x;
    const int seg = (n + 1023) / 1024;
    const int beg = tid * seg;
    int local[20];
    int sum = 0;
    #pragma unroll
    for (int j = 0; j < 20; j++) {
        int i = beg + j;
        int v = (j < seg && i < n) ? cnt[i] : 0;
        local[j] = sum;
        sum += v;
    }
    sh[tid] = sum;
    __syncthreads();
    #pragma unroll
    for (int o = 1; o < 1024; o <<= 1) {
        int x = (tid >= o) ? sh[tid - o] : 0;
        __syncthreads();
        sh[tid] += x;
        __syncthreads();
    }
    int base = (tid > 0) ? sh[tid - 1] : 0;
    #pragma unroll
    for (int j = 0; j < 20; j++) {
        int i = beg + j;
        if (j < seg && i < n) off[i] = base + local[j];
    }
    if (tid == 1023) off[n] = sh[1023];
}
__global__ void csr_place(const int* __restrict__ src, const int* __restrict__ dst,
                          const int* __restrict__ off, int* __restrict__ cur,
                          int* __restrict__ dsts, int* __restrict__ srcs, int E) {
    int i = blockIdx.x * blockDim.x + threadIdx.x;
    if (i >= E) return;
    int u = src[i];
    int p = off[u] + atomicAdd(&cur[u], 1);
    dsts[p] = dst[i];
    srcs[p] = u;
}

// ---------------- GAT aggregation (reads 4-way dot partials) ----------------
__global__ void gat_aggregate(const int* __restrict__ off, const int* __restrict__ dsts,
                              const float* __restrict__ sv, const float* __restrict__ tv,
                              const float* __restrict__ hw, float* __restrict__ hout) {
    __shared__ float sh_e[512];
    int u = blockIdx.x;
    int c = threadIdx.x;
    int beg = off[u], end = off[u + 1];
    float su = sv[u] + sv[MPAD + u] + sv[2 * MPAD + u] + sv[3 * MPAD + u];
    float4 acc = make_float4(0.f, 0.f, 0.f, 0.f);
    float dsum = 0.f;
    for (int w = beg; w < end; w += 512) {
        int we = w + 512 < end ? w + 512 : end;
        for (int j = w + c; j < we; j += 128) {
            int d = dsts[j];
            float td = tv[d] + tv[MPAD + d] + tv[2 * MPAD + d] + tv[3 * MPAD + d];
            float sc = su + td;
            float lr = sc > 0.f ? sc : 0.2f * sc;
            sh_e[j - w] = expf(-lr);
        }
        __syncthreads();
        int p = w;
        for (; p + 1 < we; p += 2) {
            int d0 = dsts[p], d1 = dsts[p + 1];
            float e0 = sh_e[p - w], e1 = sh_e[p + 1 - w];
            float4 v0 = *(reinterpret_cast<const float4*>(hw + (size_t)d0 * HDIM) + c);
            float4 v1 = *(reinterpret_cast<const float4*>(hw + (size_t)d1 * HDIM) + c);
            dsum += e0 + e1;
            acc.x += e0 * v0.x + e1 * v1.x;
            acc.y += e0 * v0.y + e1 * v1.y;
            acc.z += e0 * v0.z + e1 * v1.z;
            acc.w += e0 * v0.w + e1 * v1.w;
        }
        if (p < we) {
            int d = dsts[p];
            float ev = sh_e[p - w];
            float4 v = *(reinterpret_cast<const float4*>(hw + (size_t)d * HDIM) + c);
            dsum += ev;
            acc.x += ev * v.x; acc.y += ev * v.y;
            acc.z += ev * v.z; acc.w += ev * v.w;
        }
        __syncthreads();
    }
    float inv = 1.f / (dsum + 1e-10f);
    float4 o;
    o.x = fmaxf(acc.x * inv, 0.f);
    o.y = fmaxf(acc.y * inv, 0.f);
    o.z = fmaxf(acc.z * inv, 0.f);
    o.w = fmaxf(acc.w * inv, 0.f);
    *(reinterpret_cast<float4*>(hout + (size_t)u * HDIM) + c) = o;
}

// ---------------- final GEMV + sigmoid ----------------
__global__ void gemv_sigmoid(const float* __restrict__ h2, const float* __restrict__ v3,
                             const float* __restrict__ vb3, float* __restrict__ out, int n) {
    int warp = (blockIdx.x * blockDim.x + threadIdx.x) >> 5;
    int lane = threadIdx.x & 31;
    if (warp >= n) return;
    const float* row = h2 + (size_t)warp * HDIM;
    float acc = 0.f;
    #pragma unroll 4
    for (int c = lane; c < HDIM; c += 32) acc += row[c] * v3[c];
    #pragma unroll
    for (int o = 16; o; o >>= 1) acc += __shfl_down_sync(0xffffffffu, acc, o);
    if (lane == 0) {
        float x = acc + vb3[0];
        out[warp] = 1.f / (1.f + expf(-x));
    }
}

// ---------------- host launcher ----------------
extern "C" void kernel_launch(void* const* d_in, const int* in_sizes, int n_in,
                              void* d_out, int out_size) {
    const float* feat = (const float*)d_in[0];
    const float* goal = (const float*)d_in[1];
    const float* info = (const float*)d_in[2];
    const int*   esrc = (const int*)d_in[3];
    const int*   edst = (const int*)d_in[4];
    const float* W1   = (const float*)d_in[5];
    const float* b1   = (const float*)d_in[6];
    const float* W2   = (const float*)d_in[7];
    const float* b2   = (const float*)d_in[8];
    const float* W3   = (const float*)d_in[9];
    const float* b3   = (const float*)d_in[10];
    const float* V1   = (const float*)d_in[11];
    const float* vb1  = (const float*)d_in[12];
    const float* V2   = (const float*)d_in[13];
    const float* vb2  = (const float*)d_in[14];
    const float* V3   = (const float*)d_in[15];
    const float* vb3  = (const float*)d_in[16];
    const float* gatW = (const float*)d_in[17];
    const float* gatA = (const float*)d_in[18];
    float* out = (float*)d_out;

    int E = in_sizes[3];
    if (E > E_CAP) E = E_CAP;
    const int n = N_NODES;

    float *h, *hw, *acc, *sp, *tp;
    int *cnt, *off, *cur, *dsts, *srcs;
    uint32_t *Bh, *Bl, *A1h, *A1l, *A2h, *A2l;
    cudaGetSymbolAddress((void**)&h,   g_h);
    cudaGetSymbolAddress((void**)&hw,  g_hw);
    cudaGetSymbolAddress((void**)&acc, g_acc);
    cudaGetSymbolAddress((void**)&sp,  g_sp);
    cudaGetSymbolAddress((void**)&tp,  g_tp);
    cudaGetSymbolAddress((void**)&cnt, g_cnt);
    cudaGetSymbolAddress((void**)&off, g_off);
    cudaGetSymbolAddress((void**)&cur, g_cur);
    cudaGetSymbolAddress((void**)&dsts,g_dsts);
    cudaGetSymbolAddress((void**)&srcs,g_srcs);
    cudaGetSymbolAddress((void**)&Bh,  g_Bh);
    cudaGetSymbolAddress((void**)&Bl,  g_Bl);
    cudaGetSymbolAddress((void**)&A1h, g_A1h);
    cudaGetSymbolAddress((void**)&A1l, g_A1l);
    cudaGetSymbolAddress((void**)&A2h, g_A2h);
    cudaGetSymbolAddress((void**)&A2l, g_A2l);

    static bool attr_done = false;
    if (!attr_done) {
        cudaFuncSetAttribute(gemm_pp<1,1,0>, cudaFuncAttributeMaxDynamicSharedMemorySize, SM_BYTES);
        cudaFuncSetAttribute(gemm_pp<0,1,0>, cudaFuncAttributeMaxDynamicSharedMemorySize, SM_BYTES);
        cudaFuncSetAttribute(gemm_pp<0,0,1>, cudaFuncAttributeMaxDynamicSharedMemorySize, SM_BYTES);
        cudaFuncSetAttribute(gemm_pp<1,0,0>, cudaFuncAttributeMaxDynamicSharedMemorySize, SM_BYTES);
        attr_done = true;
    }

    const dim3 gg(NBLK_PERSIST);
    const dim3 cg_f(157, K2_FEAT / 16);
    const dim3 cg_h(157, K2_H / 16);
    const int node_warp_blocks = (n * 32 + 255) / 256;
    const int edge_blocks = (E + 255) / 256;

    #define BW(o) (Bh + (size_t)(o) * HDIM), (Bl + (size_t)(o) * HDIM)

    // ---- input chain ----
    split_all<<<(K2_TOTAL * HDIM + 255) / 256, 256>>>(W1, V1, W2, W3, V2, gatW, Bh, Bl);
    conv_a<1><<<cg_f, 256>>>(feat, goal, info, A1h, A1l, n, FEAT);
    gemm_pp<1,1,0><<<gg, 256, SM_BYTES>>>(A1h, A1l, BW(OFF_W1), b1, nullptr, A2h, A2l,
                                          nullptr, nullptr, nullptr, n, K2_FEAT / 16);
    gemm_pp<1,1,0><<<gg, 256, SM_BYTES>>>(A2h, A2l, BW(OFF_W2), b2, nullptr, A1h, A1l,
                                          nullptr, nullptr, nullptr, n, K2_H / 16);
    gemm_pp<0,1,0><<<gg, 256, SM_BYTES>>>(A1h, A1l, BW(OFF_W3), b3, nullptr, A2h, A2l,
                                          nullptr, nullptr, nullptr, n, K2_H / 16);

    // ---- CSR build ----
    zero2<<<(n + 255) / 256, 256>>>(cnt, cur, n);
    csr_count<<<edge_blocks, 256>>>(esrc, cnt, E);
    csr_scan<<<1, 1024>>>(cnt, off, n);
    csr_place<<<edge_blocks, 256>>>(esrc, edst, off, cur, dsts, srcs, E);

    // ---- GAT layers ----
    for (int l = 0; l < NUM_GAT; l++) {
        const float* al = gatA + (size_t)l * 2 * HDIM;
        zero_sp<<<(4 * MPAD + 255) / 256, 256>>>(sp, tp);
        gemm_pp<0,0,1><<<gg, 256, SM_BYTES>>>(A2h, A2l, BW(OFF_GAT0 + l * K2_H),
                                              nullptr, hw, nullptr, nullptr,
                                              al, sp, tp, n, K2_H / 16);
        gat_aggregate<<<n, 128>>>(off, dsts, sp, tp, hw, h);
        if (l < NUM_GAT - 1)
            conv_a<0><<<cg_h, 256>>>(h, nullptr, nullptr, A2h, A2l, n, HDIM);
    }

    // ---- output MLP ----
    conv_a<1><<<cg_f, 256>>>(h, goal, info, A1h, A1l, n, FEAT);
    gemm_pp<1,1,0><<<gg, 256, SM_BYTES>>>(A1h, A1l, BW(OFF_V1), vb1, nullptr, A2h, A2l,
                                          nullptr, nullptr, nullptr, n, K2_FEAT / 16);
    gemm_pp<1,0,0><<<gg, 256, SM_BYTES>>>(A2h, A2l, BW(OFF_V2), vb2, acc, nullptr, nullptr,
                                          nullptr, nullptr, nullptr, n, K2_H / 16);
    gemv_sigmoid<<<node_warp_blocks, 256>>>(acc, V3, vb3, out, n);
}